// round 16
// baseline (speedup 1.0000x reference)
#include <cuda_runtime.h>

#define S_LEN   2048
#define E_DIM   1024
#define NHEADS  16
#define HD      64
#define MAXR    2048
#define KSPLIT  16     // proj K-splits (64 k each)
#define RCAP    128    // rows covered by the split partial-buffer path
#define ASTR    260    // proj A-dup smem row stride (floats)
#define KBSTR   68     // attn smem row stride (floats); 68/4=17 odd -> conflict-free float4

// ---------------- device scratch (static, no runtime allocation) ----------------
__device__ int   g_lo, g_ns;
__device__ float g_xsum[E_DIM];       // zero at load; re-zeroed by k_out for next call
__device__ float g_vtot[E_DIM];
__device__ float g_qp[KSPLIT][RCAP * E_DIM];
__device__ float g_kp[KSPLIT][RCAP * E_DIM];
__device__ float g_vp[KSPLIT][RCAP * E_DIM];
__device__ float g_q[MAXR * E_DIM];   // dense fallback rows (overflow path)
__device__ float g_k[MAXR * E_DIM];
__device__ float g_v[MAXR * E_DIM];
__device__ float g_c[NHEADS * S_LEN]; // per-head softmax column sums
__device__ float g_w0[NHEADS];

// ---------------- f32x2 packed helpers ----------------
__device__ __forceinline__ void upk2(unsigned long long v, float& lo, float& hi) {
    asm("mov.b64 {%0,%1}, %2;" : "=f"(lo), "=f"(hi) : "l"(v));
}
__device__ __forceinline__ void ffma2(unsigned long long& d, unsigned long long a,
                                      unsigned long long b) {
    asm("fma.rn.f32x2 %0, %1, %2, %0;" : "+l"(d) : "l"(a), "l"(b));
}

// ---------------- K-A1: colsum -> g_xsum atomics + zero scratch (branch A) ----------------
// grid 128 blocks (32 row-chunks x 4 col-slabs), 256 threads
__global__ void __launch_bounds__(256) k_pre(const float* __restrict__ x,
                                             float* __restrict__ dout) {
    __shared__ float4 part[4][64];
    int bid = blockIdx.x, tid = threadIdx.x;
    int by  = bid >> 2;              // row chunk (64 rows)
    int cb  = (bid & 3) * 64;        // f4-column base
    int sub = tid >> 6, col4 = tid & 63;
    const float4* x4 = (const float4*)x;
    int r0 = by * 64 + sub * 16;
    float4 a = make_float4(0.f, 0.f, 0.f, 0.f);
#pragma unroll
    for (int r = 0; r < 16; ++r) {
        float4 t = x4[(size_t)(r0 + r) * (E_DIM / 4) + cb + col4];
        a.x += t.x; a.y += t.y; a.z += t.z; a.w += t.w;
    }
    part[sub][col4] = a;
    // zero scratch while loads are in flight
    g_c[bid * 256 + tid] = 0.f;                  // 128*256 = NHEADS*S_LEN
    if (bid < 4) dout[bid * 256 + tid] = 0.f;
    if (bid == 4 && tid < NHEADS) g_w0[tid] = 0.f;
    __syncthreads();
    if (sub == 0) {
        float4 s  = part[0][col4];
        float4 t1 = part[1][col4], t2 = part[2][col4], t3 = part[3][col4];
        s.x += t1.x + t2.x + t3.x;
        s.y += t1.y + t2.y + t3.y;
        s.z += t1.z + t2.z + t3.z;
        s.w += t1.w + t2.w + t3.w;
        int c = 4 * (cb + col4);
        atomicAdd(&g_xsum[c + 0], s.x);
        atomicAdd(&g_xsum[c + 1], s.y);
        atomicAdd(&g_xsum[c + 2], s.z);
        atomicAdd(&g_xsum[c + 3], s.w);
    }
}

// ---------------- K-A2: vtot = xsum @ Wv + S*bv  (branch A, 32 blocks) ----------------
__global__ void __launch_bounds__(256) k_vtot(const float* __restrict__ Wv,
                                              const float* __restrict__ bv) {
    __shared__ float red[8][32];
    int tid = threadIdx.x;
    int d = tid & 31, kr = tid >> 5;     // 32 dims x 8 k-ranges of 128
    int dim = blockIdx.x * 32 + d;
    float a0 = 0.f, a1 = 0.f, a2 = 0.f, a3 = 0.f;
    int k0 = kr * 128;
#pragma unroll 8
    for (int k = k0; k < k0 + 128; k += 4) {
        a0 += g_xsum[k]     * Wv[(size_t)k       * E_DIM + dim];
        a1 += g_xsum[k + 1] * Wv[(size_t)(k + 1) * E_DIM + dim];
        a2 += g_xsum[k + 2] * Wv[(size_t)(k + 2) * E_DIM + dim];
        a3 += g_xsum[k + 3] * Wv[(size_t)(k + 3) * E_DIM + dim];
    }
    red[kr][d] = (a0 + a1) + (a2 + a3);
    __syncthreads();
    if (tid < 32) {
        int dm = blockIdx.x * 32 + tid;
        float s = red[0][tid] + red[1][tid] + red[2][tid] + red[3][tid]
                + red[4][tid] + red[5][tid] + red[6][tid] + red[7][tid]
                + (float)S_LEN * bv[dm];
        g_vtot[dm] = s;
    }
}

// ---------------- proj helpers ----------------
// tile worker: M = 8*R rows, N = 128 cols, K = 64 (one split), full preload
template<int R>
__device__ __forceinline__ void proj_run(
    const float* __restrict__ x, const float* __restrict__ W,
    const float* __restrict__ bias, float* __restrict__ outp,
    int lo, int ns, int nrows, int kbase, bool addBias,
    float* As_d, float* Bs, int colbase)
{
    int tid = threadIdx.x;
    int tx = tid & 31, ty = tid >> 5;
#pragma unroll
    for (int u = 0; u < 8; u++) {
        int idx = tid + 256 * u;
        int r = idx >> 5, c4 = idx & 31;
        *(float4*)&Bs[r * 128 + c4 * 4] =
            *(const float4*)&W[(size_t)(kbase + r) * E_DIM + colbase + c4 * 4];
    }
#pragma unroll
    for (int u = 0; u < R / 2; u++) {
        int idx = tid + 256 * u;
        int r = idx >> 4, k4 = idx & 15;
        float4 v = (r < ns) ? *(const float4*)&x[(size_t)(lo + r) * E_DIM + kbase + 4 * k4]
                            : make_float4(0.f, 0.f, 0.f, 0.f);
        float vv[4] = {v.x, v.y, v.z, v.w};
#pragma unroll
        for (int i = 0; i < 4; i++) {
            float2 d2; d2.x = vv[i]; d2.y = vv[i];
            *(float2*)&As_d[(4 * k4 + i) * ASTR + 2 * r] = d2;
        }
    }
    __syncthreads();

    unsigned long long acc[R][2];
#pragma unroll
    for (int r = 0; r < R; r++) { acc[r][0] = 0ULL; acc[r][1] = 0ULL; }

#pragma unroll 4
    for (int kk = 0; kk < 64; kk++) {
        const ulonglong2* ap = (const ulonglong2*)&As_d[kk * ASTR + 2 * R * ty];
        unsigned long long b0 = *(const unsigned long long*)&Bs[kk * 128 + 2 * tx];
        unsigned long long b1 = *(const unsigned long long*)&Bs[kk * 128 + 2 * tx + 64];
#pragma unroll
        for (int q = 0; q < R / 2; q++) {
            ulonglong2 t = ap[q];
            ffma2(acc[2 * q][0],     t.x, b0); ffma2(acc[2 * q][1],     t.x, b1);
            ffma2(acc[2 * q + 1][0], t.y, b0); ffma2(acc[2 * q + 1][1], t.y, b1);
        }
    }
#pragma unroll
    for (int r = 0; r < R; r++) {
        int gr = R * ty + r;
        if (gr >= nrows) continue;
#pragma unroll
        for (int p = 0; p < 2; p++) {
            float v0, v1;
            upk2(acc[r][p], v0, v1);
            int c0 = colbase + 2 * tx + 64 * p;
            if (addBias) {
                v0 += bias[c0];
                v1 += bias[c0 + 1];
            }
            float2 st2; st2.x = v0; st2.y = v1;
            *(float2*)&outp[(size_t)gr * E_DIM + c0] = st2;
        }
    }
}

// ---------------- K-B1: projections (self-bounds; split-K into partial buffers) ----------------
__global__ void __launch_bounds__(256) k_proj(
    const float* __restrict__ x,
    const int* __restrict__ seg, const int* __restrict__ pos,
    const float* __restrict__ W0, const float* __restrict__ W1,
    const float* __restrict__ W2,
    const float* __restrict__ b0, const float* __restrict__ b1,
    const float* __restrict__ b2) {
    extern __shared__ float sm[];
    float* As_d = sm;               // [64][ASTR]
    float* Bs   = sm + 64 * ASTR;   // [64][128]
    __shared__ int sb[2];
    int tid = threadIdx.x;

    // --- self-computed segment bounds (int4 scan of seg) ---
    if (tid < 2) sb[tid] = 0;
    __syncthreads();
    {
        int t = seg[pos[0]];
        int lo = 0, cnt = 0;
        const int4* seg4 = (const int4*)seg;
        for (int i = tid; i < S_LEN / 4; i += 256) {
            int4 v = seg4[i];
            lo  += (v.x <  t) + (v.y <  t) + (v.z <  t) + (v.w <  t);
            cnt += (v.x == t) + (v.y == t) + (v.z == t) + (v.w == t);
        }
        atomicAdd(&sb[0], lo);
        atomicAdd(&sb[1], cnt);
    }
    __syncthreads();
    int lo = sb[0], ns = sb[1];
    if (tid == 0) { g_lo = lo; g_ns = ns; }   // benign same-value multi-store; read by successors

    int mat = blockIdx.z, kb = blockIdx.y;
    const float* W    = (mat == 0) ? W0 : ((mat == 1) ? W1 : W2);
    const float* bias = (mat == 0) ? b0 : ((mat == 1) ? b1 : b2);
    float* partial = (mat == 0) ? g_qp[kb] : ((mat == 1) ? g_kp[kb] : g_vp[kb]);
    float* dense   = (mat == 0) ? g_q : ((mat == 1) ? g_k : g_v);
    int colbase = blockIdx.x * 128;
    int kbase = kb * 64;
    int mrows = min(ns, RCAP);

    if      (mrows <= 64) proj_run<8>(x, W, bias, partial, lo, ns, mrows, kbase, kb == 0, As_d, Bs, colbase);
    else if (mrows <= 80) proj_run<10>(x, W, bias, partial, lo, ns, mrows, kbase, kb == 0, As_d, Bs, colbase);
    else if (mrows <= 96) proj_run<12>(x, W, bias, partial, lo, ns, mrows, kbase, kb == 0, As_d, Bs, colbase);
    else                  proj_run<16>(x, W, bias, partial, lo, ns, mrows, kbase, kb == 0, As_d, Bs, colbase);

    if (ns > RCAP && kb == 0) {   // rare overflow: dense full-K for rows >= RCAP
        for (int idx = tid; idx < (ns - RCAP) * 128; idx += 256) {
            int r = RCAP + idx / 128, c = colbase + (idx & 127);
            float acc = bias[c];
            for (int k = 0; k < E_DIM; k++)
                acc += x[(size_t)(lo + r) * E_DIM + k] * W[(size_t)k * E_DIM + c];
            dense[(size_t)r * E_DIM + c] = acc;
        }
    }
}

// ---------------- K-B2: sum split-K partials (float4, high MLP) ----------------
__global__ void __launch_bounds__(256) k_reduce() {
    int ns = g_ns;
    int total = min(ns, RCAP) * E_DIM;
    int base = blockIdx.x * 1024 + threadIdx.x * 4;
    if (base >= total) return;
    int arr = blockIdx.y;
    const float* src = (arr == 0) ? &g_qp[0][0] : ((arr == 1) ? &g_kp[0][0] : &g_vp[0][0]);
    float* dst = (arr == 0) ? g_q : ((arr == 1) ? g_k : g_v);
    float4 s = make_float4(0.f, 0.f, 0.f, 0.f);
#pragma unroll
    for (int p = 0; p < KSPLIT; p++) {
        float4 t = *(const float4*)&src[(size_t)p * (RCAP * E_DIM) + base];
        s.x += t.x; s.y += t.y; s.z += t.z; s.w += t.w;
    }
    *(float4*)&dst[base] = s;
}

// ---------------- dot: q row (smem) . k row (smem), 64 dims, f32x2 ----------------
__device__ __forceinline__ float dot64(const float* qrow, const float* krow) {
    const ulonglong2* qp = (const ulonglong2*)qrow;
    const ulonglong2* kp = (const ulonglong2*)krow;
    unsigned long long s01 = 0ULL, s23 = 0ULL;
#pragma unroll
    for (int d4 = 0; d4 < 16; d4++) {
        ulonglong2 qv = qp[d4];
        ulonglong2 kv = kp[d4];
        ffma2(s01, qv.x, kv.x);
        ffma2(s23, qv.y, kv.y);
    }
    float e0, e1, e2, e3;
    upk2(s01, e0, e1); upk2(s23, e2, e3);
    return (e0 + e1) + (e2 + e3);
}

// ---------------- K-J1: per-head attention column sums (direct REDG out) ----------------
// grid (NHEADS, 8 row-blocks), 256 threads (8 warps, one row per warp per group)
__global__ void __launch_bounds__(256) k_attn() {
    extern __shared__ float sm[];
    float* kbuf = sm;                    // [128][KBSTR]
    float* qr   = kbuf + 128 * KBSTR;    // [8][KBSTR]

    int h = blockIdx.x, rb = blockIdx.y, ns = g_ns;
    int tid = threadIdx.x, w = tid >> 5, lane = tid & 31;
    int zc = S_LEN - ns;
    const float* qh = g_q + h * HD;
    const float* kh = g_k + h * HD;
    float* cg = g_c + h * S_LEN;

    if (ns <= 128) {
        // ---------- fast static path ----------
        for (int idx = tid; idx < ns * 16; idx += 256) {
            int j = idx >> 4, d4 = idx & 15;
            *(float4*)&kbuf[j * KBSTR + 4 * d4] =
                *(const float4*)&kh[(size_t)j * E_DIM + 4 * d4];
        }
        __syncthreads();
        int ngroups = (ns + 63) >> 6;
        for (int g = 0; g < ngroups; g++) {
            int i = g * 64 + rb * 8 + w;
            bool active = (i < ns);
            if (active && lane < 16)
                *(float4*)&qr[w * KBSTR + 4 * lane] =
                    *(const float4*)&qh[(size_t)i * E_DIM + 4 * lane];
            __syncwarp();
            if (active) {
                float sreg[4];
                float m = -1e30f;
                int nt = (ns + 31) >> 5;          // warp-uniform dot count
#pragma unroll
                for (int t = 0; t < 4; t++) {
                    if (t >= nt) break;
                    int j = t * 32 + lane;
                    int jj = (j < ns) ? j : (ns - 1);   // clamp: safe smem read
                    float s = dot64(&qr[w * KBSTR], &kbuf[jj * KBSTR]);
                    sreg[t] = (j < ns) ? s : -1e30f;
                    m = fmaxf(m, sreg[t]);
                }
#pragma unroll
                for (int o = 16; o > 0; o >>= 1)
                    m = fmaxf(m, __shfl_xor_sync(0xffffffffu, m, o));
                if (zc > 0) m = fmaxf(m, 0.f);    // masked entries are ZERO, not -inf
                float e[4];
                float Z = 0.f;
#pragma unroll
                for (int t = 0; t < 4; t++) {
                    if (t >= nt) break;
                    int j = t * 32 + lane;
                    e[t] = (j < ns) ? __expf(sreg[t] - m) : 0.f;
                    Z += e[t];
                }
#pragma unroll
                for (int o = 16; o > 0; o >>= 1)
                    Z += __shfl_xor_sync(0xffffffffu, Z, o);
                Z += (float)zc * __expf(-m);
                float invZ = 1.f / Z;
#pragma unroll
                for (int t = 0; t < 4; t++) {
                    if (t >= nt) break;
                    int j = t * 32 + lane;
                    if (j < ns) atomicAdd(&cg[j], e[t] * invZ);   // REDG
                }
                if (lane == 0) atomicAdd(&g_w0[h], __expf(-m) * invZ);
            }
        }
    } else {
        // ---------- general chunked path (ns > 128, effectively never) ----------
        const int JT = 128;
        __shared__ int s_loaded;
        if (tid == 0) s_loaded = -1;
        __syncthreads();
        int nchunks = (ns + JT - 1) / JT;
        int ngroups = (ns + 63) / 64;
        for (int g = 0; g < ngroups; g++) {
            int i = g * 64 + rb * 8 + w;
            bool active = (i < ns);
            if (active && lane < 16)
                *(float4*)&qr[w * KBSTR + 4 * lane] =
                    *(const float4*)&qh[(size_t)i * E_DIM + 4 * lane];
            __syncwarp();
            float m = -1e30f, Z = 0.f;
            for (int c = 0; c < nchunks; c++) {
                int c0 = c * JT, cl = min(JT, ns - c0);
                if (s_loaded != c) {
                    __syncthreads();
                    for (int idx = tid; idx < cl * 16; idx += 256) {
                        int j = idx >> 4, d4 = idx & 15;
                        *(float4*)&kbuf[j * KBSTR + 4 * d4] =
                            *(const float4*)&kh[(size_t)(c0 + j) * E_DIM + 4 * d4];
                    }
                    if (tid == 0) s_loaded = c;
                    __syncthreads();
                }
                if (active)
                    for (int j = lane; j < cl; j += 32) {
                        float s = dot64(&qr[w * KBSTR], &kbuf[j * KBSTR]);
                        float mn = fmaxf(m, s);
                        Z = Z * __expf(m - mn) + __expf(s - mn);
                        m = mn;
                    }
            }
            float mrow = 0.f, invZ = 0.f;
            if (active) {
                mrow = m;
#pragma unroll
                for (int o = 16; o > 0; o >>= 1)
                    mrow = fmaxf(mrow, __shfl_xor_sync(0xffffffffu, mrow, o));
                if (zc > 0) mrow = fmaxf(mrow, 0.f);
                float z = Z * __expf(m - mrow);
#pragma unroll
                for (int o = 16; o > 0; o >>= 1)
                    z += __shfl_xor_sync(0xffffffffu, z, o);
                z += (float)zc * __expf(-mrow);
                invZ = 1.f / z;
            }
            for (int c = 0; c < nchunks; c++) {
                int c0 = c * JT, cl = min(JT, ns - c0);
                if (s_loaded != c) {
                    __syncthreads();
                    for (int idx = tid; idx < cl * 16; idx += 256) {
                        int j = idx >> 4, d4 = idx & 15;
                        *(float4*)&kbuf[j * KBSTR + 4 * d4] =
                            *(const float4*)&kh[(size_t)(c0 + j) * E_DIM + 4 * d4];
                    }
                    if (tid == 0) s_loaded = c;
                    __syncthreads();
                }
                if (active)
                    for (int j = lane; j < cl; j += 32) {
                        float s = dot64(&qr[w * KBSTR], &kbuf[j * KBSTR]);
                        atomicAdd(&cg[c0 + j], __expf(s - mrow) * invZ);
                    }
            }
            if (active && lane == 0) atomicAdd(&g_w0[h], __expf(-mrow) * invZ);
        }
    }
}

// ---------------- K-J2: att slice from c/w0/V/vtot, then vecmat out = att @ Wo + bo ----------------
// grid (4 coltiles of 256, 32 kslices of 32), 256 threads
__global__ void __launch_bounds__(256) k_out(const float* __restrict__ Wo,
                                             const float* __restrict__ bo,
                                             float* __restrict__ dout) {
    __shared__ float c_s[S_LEN];
    __shared__ float red[8][32];
    __shared__ float att_s[32];
    int ky = blockIdx.y;
    int k0 = ky * 32;             // global att-dim base
    int h  = ky >> 1;             // owning head
    int ns = g_ns;
    int tid = threadIdx.x;
    int d = tid & 31, part = tid >> 5;   // 8 j-parts x 32 dims
    float w0 = g_w0[h];

    for (int i = tid; i < ns; i += 256) c_s[i] = g_c[h * S_LEN + i];
    __syncthreads();

    {
        float a0 = 0.f, a1 = 0.f;
        int j = part;
        for (; j + 8 < ns; j += 16) {
            a0 += (c_s[j]     - w0) * g_v[(size_t)j       * E_DIM + k0 + d];
            a1 += (c_s[j + 8] - w0) * g_v[(size_t)(j + 8) * E_DIM + k0 + d];
        }
        for (; j < ns; j += 8)
            a0 += (c_s[j] - w0) * g_v[(size_t)j * E_DIM + k0 + d];
        red[part][d] = a0 + a1;
    }
    __syncthreads();
    if (tid < 32) {
        float tot = red[0][d] + red[1][d] + red[2][d] + red[3][d]
                  + red[4][d] + red[5][d] + red[6][d] + red[7][d]
                  + w0 * g_vtot[k0 + d];
        att_s[d] = tot / (float)ns;
    }
    __syncthreads();

    int c = blockIdx.x * 256 + tid;
    float acc = (ky == 0) ? bo[c] : 0.f;
#pragma unroll
    for (int kk = 0; kk < 32; kk++)
        acc += att_s[kk] * Wo[(size_t)(k0 + kk) * E_DIM + c];
    atomicAdd(&dout[c], acc);

    // re-zero g_xsum for the NEXT call (this call's vtot already consumed it)
    if (ky == 0) g_xsum[blockIdx.x * 256 + tid] = 0.f;
}

// ---------------- launch: forked-graph capture ----------------
#define PROJ_SMEM ((64 * ASTR + 64 * 128) * 4)
#define ATTN_SMEM ((128 * KBSTR + 8 * KBSTR) * 4)

extern "C" void kernel_launch(void* const* d_in, const int* in_sizes, int n_in,
                              void* d_out, int out_size) {
    const float* x   = (const float*)d_in[0];
    const int*   seg = (const int*)d_in[1];
    const int*   pos = (const int*)d_in[2];
    const float* Wq = (const float*)d_in[3];
    const float* bq = (const float*)d_in[4];
    const float* Wk = (const float*)d_in[5];
    const float* bk = (const float*)d_in[6];
    const float* Wv = (const float*)d_in[7];
    const float* bv = (const float*)d_in[8];
    const float* Wo = (const float*)d_in[9];
    const float* bo = (const float*)d_in[10];
    float* out = (float*)d_out;

    cudaFuncSetAttribute(k_proj, cudaFuncAttributeMaxDynamicSharedMemorySize, PROJ_SMEM);
    cudaFuncSetAttribute(k_attn, cudaFuncAttributeMaxDynamicSharedMemorySize, ATTN_SMEM);

    // fork a side branch off the capture (legacy) stream
    cudaStream_t s2;
    cudaEvent_t eFork, eJoin;
    cudaStreamCreateWithFlags(&s2, cudaStreamNonBlocking);
    cudaEventCreateWithFlags(&eFork, cudaEventDisableTiming);
    cudaEventCreateWithFlags(&eJoin, cudaEventDisableTiming);

    cudaEventRecord(eFork, 0);
    cudaStreamWaitEvent(s2, eFork, 0);

    // branch A: colsum + zeroing, then vtot
    k_pre<<<128, 256, 0, s2>>>(x, out);
    k_vtot<<<32, 256, 0, s2>>>(Wv, bv);
    cudaEventRecord(eJoin, s2);

    // branch B (main): projections (self-bounds) + split-K reduce
    k_proj<<<dim3(8, KSPLIT, 3), 256, PROJ_SMEM>>>(x, seg, pos,
                                                   Wq, Wk, Wv, bq, bk, bv);
    k_reduce<<<dim3(RCAP, 3), 256>>>();

    // join, then attention + output
    cudaStreamWaitEvent(0, eJoin, 0);
    k_attn<<<dim3(NHEADS, 8), 256, ATTN_SMEM>>>();
    k_out<<<dim3(4, 32), 256>>>(Wo, bo, out);

    // handles intentionally not destroyed: kernel_launch is invoked only a
    // bounded number of times (correctness + capture); destroying objects that
    // participate in an active capture would invalidate the graph.
}

// round 17
// speedup vs baseline: 1.0978x; 1.0978x over previous
#include <cuda_runtime.h>

#define S_LEN   2048
#define E_DIM   1024
#define NHEADS  16
#define HD      64
#define MAXR    2049   // ns rows + 1 virtual row (xsum -> vtot)
#define KSPLIT  16     // proj K-splits (64 k each)
#define RCAP    128    // rows covered by the REDG-accumulate path
#define XS      32     // colsum row splits
#define ASTR    260    // proj A-dup smem row stride (floats)
#define KBSTR   68     // attn smem row stride (floats); 68/4=17 odd -> conflict-free float4

// ---------------- device scratch (static, no runtime allocation) ----------------
__device__ int   g_lo, g_ns;
__device__ float g_xsump[XS][E_DIM];
__device__ float g_q[MAXR * E_DIM];
__device__ float g_k[MAXR * E_DIM];
__device__ float g_v[MAXR * E_DIM];   // row ns = vtot
__device__ float g_c[NHEADS * S_LEN]; // per-head softmax column sums
__device__ float g_w0[NHEADS];

// ---------------- f32x2 packed helpers ----------------
__device__ __forceinline__ void upk2(unsigned long long v, float& lo, float& hi) {
    asm("mov.b64 {%0,%1}, %2;" : "=f"(lo), "=f"(hi) : "l"(v));
}
__device__ __forceinline__ void ffma2(unsigned long long& d, unsigned long long a,
                                      unsigned long long b) {
    asm("fma.rn.f32x2 %0, %1, %2, %0;" : "+l"(d) : "l"(a), "l"(b));
}

// ---------------- K0: colsum partials + bounds + zero scratch & qkv targets ----------------
// grid 128 blocks, 256 threads
__global__ void __launch_bounds__(256) k_pre(const float* __restrict__ x,
                                             const int* __restrict__ seg,
                                             const int* __restrict__ pos,
                                             float* __restrict__ dout) {
    __shared__ float4 part[4][64];
    int bid = blockIdx.x, tid = threadIdx.x;
    int by  = bid >> 2;              // 0..31 row chunks (64 rows each)
    int cb  = (bid & 3) * 64;        // f4-column base
    int sub = tid >> 6, col4 = tid & 63;
    const float4* x4 = (const float4*)x;
    int r0 = by * 64 + sub * 16;
    float4 a = make_float4(0.f, 0.f, 0.f, 0.f);
#pragma unroll
    for (int r = 0; r < 16; ++r) {
        float4 t = x4[(size_t)(r0 + r) * (E_DIM / 4) + cb + col4];
        a.x += t.x; a.y += t.y; a.z += t.z; a.w += t.w;
    }
    part[sub][col4] = a;
    // zero scratch while loads are in flight
    g_c[bid * 256 + tid] = 0.f;                  // 128*256 = NHEADS*S_LEN
    if (bid < 4) dout[bid * 256 + tid] = 0.f;
    if (bid == 4 && tid < NHEADS) g_w0[tid] = 0.f;
    {   // zero first RCAP rows of g_q/g_k/g_v (REDG accumulate targets)
        const float4 z = make_float4(0.f, 0.f, 0.f, 0.f);
        int i0 = bid * 256 + tid;                // 0..32767 over grid
#pragma unroll
        for (int u = 0; u < 1; u++) { }          // (RCAP*E_DIM/4 = 32768 = grid*256)
        ((float4*)g_q)[i0] = z;
        ((float4*)g_k)[i0] = z;
        ((float4*)g_v)[i0] = z;
    }
    __syncthreads();
    if (sub == 0) {
        float4 s  = part[0][col4];
        float4 t1 = part[1][col4], t2 = part[2][col4], t3 = part[3][col4];
        s.x += t1.x + t2.x + t3.x;
        s.y += t1.y + t2.y + t3.y;
        s.z += t1.z + t2.z + t3.z;
        s.w += t1.w + t2.w + t3.w;
        *(float4*)&g_xsump[by][4 * (cb + col4)] = s;
    }
    if (bid == 0) {
        __shared__ int s_lo, s_cnt, s_t;
        if (tid == 0) { s_t = seg[pos[0]]; s_lo = 0; s_cnt = 0; }
        __syncthreads();
        int t = s_t, lo = 0, cnt = 0;
        for (int i = tid; i < S_LEN; i += 256) {
            int v = seg[i];
            lo  += (v <  t);
            cnt += (v == t);
        }
        atomicAdd(&s_lo, lo);
        atomicAdd(&s_cnt, cnt);
        __syncthreads();
        if (tid == 0) { g_lo = s_lo; g_ns = s_cnt; }
    }
}

// ---------------- proj helpers ----------------
__device__ __forceinline__ float4 proj_ldA(const float* __restrict__ x,
                                           int lo, int ns, int mat, int gr, int kidx) {
    if (gr < ns) return *(const float4*)&x[(size_t)(lo + gr) * E_DIM + kidx];
    if (gr == ns && mat == 2) {
        float4 s = make_float4(0.f, 0.f, 0.f, 0.f);
#pragma unroll
        for (int p = 0; p < XS; p++) {
            float4 t = *(const float4*)&g_xsump[p][kidx];
            s.x += t.x; s.y += t.y; s.z += t.z; s.w += t.w;
        }
        return s;
    }
    return make_float4(0.f, 0.f, 0.f, 0.f);
}

// tile worker: M = 8*R rows, N = 128 cols, K = 64 (one split), full preload
// epilogue: REDG atomicAdd into pre-zeroed dense output
template<int R>
__device__ __forceinline__ void proj_run(
    const float* __restrict__ x, const float* __restrict__ W,
    const float* __restrict__ bias, float* __restrict__ outp,
    int lo, int ns, int nrows, int mat, int kbase, bool addBias,
    float* As_d, float* Bs, int colbase)
{
    int tid = threadIdx.x;
    int tx = tid & 31, ty = tid >> 5;
#pragma unroll
    for (int u = 0; u < 8; u++) {
        int idx = tid + 256 * u;
        int r = idx >> 5, c4 = idx & 31;
        *(float4*)&Bs[r * 128 + c4 * 4] =
            *(const float4*)&W[(size_t)(kbase + r) * E_DIM + colbase + c4 * 4];
    }
#pragma unroll
    for (int u = 0; u < R / 2; u++) {
        int idx = tid + 256 * u;
        int r = idx >> 4, k4 = idx & 15;
        float4 v = proj_ldA(x, lo, ns, mat, r, kbase + 4 * k4);
        float vv[4] = {v.x, v.y, v.z, v.w};
#pragma unroll
        for (int i = 0; i < 4; i++) {
            float2 d2; d2.x = vv[i]; d2.y = vv[i];
            *(float2*)&As_d[(4 * k4 + i) * ASTR + 2 * r] = d2;
        }
    }
    __syncthreads();

    unsigned long long acc[R][2];
#pragma unroll
    for (int r = 0; r < R; r++) { acc[r][0] = 0ULL; acc[r][1] = 0ULL; }

#pragma unroll 4
    for (int kk = 0; kk < 64; kk++) {
        const ulonglong2* ap = (const ulonglong2*)&As_d[kk * ASTR + 2 * R * ty];
        unsigned long long b0 = *(const unsigned long long*)&Bs[kk * 128 + 2 * tx];
        unsigned long long b1 = *(const unsigned long long*)&Bs[kk * 128 + 2 * tx + 64];
#pragma unroll
        for (int q = 0; q < R / 2; q++) {
            ulonglong2 t = ap[q];
            ffma2(acc[2 * q][0],     t.x, b0); ffma2(acc[2 * q][1],     t.x, b1);
            ffma2(acc[2 * q + 1][0], t.y, b0); ffma2(acc[2 * q + 1][1], t.y, b1);
        }
    }
    // epilogue: fire-and-forget REDG accumulate (targets pre-zeroed by k_pre)
#pragma unroll
    for (int r = 0; r < R; r++) {
        int gr = R * ty + r;
        if (gr >= nrows) continue;
        bool virt = (gr == ns) && (mat == 2);
#pragma unroll
        for (int p = 0; p < 2; p++) {
            float v0, v1;
            upk2(acc[r][p], v0, v1);
            int c0 = colbase + 2 * tx + 64 * p;
            if (addBias) {
                float sc = virt ? (float)S_LEN : 1.f;
                v0 += sc * bias[c0];
                v1 += sc * bias[c0 + 1];
            }
            atomicAdd(&outp[(size_t)gr * E_DIM + c0],     v0);
            atomicAdd(&outp[(size_t)gr * E_DIM + c0 + 1], v1);
        }
    }
}

// ---------------- K2: projections (REDG accumulate into dense q/k/v) ----------------
// grid (8 coltiles x128, KSPLIT, 3 mats), 256 threads
__global__ void __launch_bounds__(256) k_proj(
    const float* __restrict__ x,
    const float* __restrict__ W0, const float* __restrict__ W1,
    const float* __restrict__ W2,
    const float* __restrict__ b0, const float* __restrict__ b1,
    const float* __restrict__ b2) {
    extern __shared__ float sm[];
    float* As_d = sm;               // [64][ASTR]
    float* Bs   = sm + 64 * ASTR;   // [64][128]
    int mat = blockIdx.z, kb = blockIdx.y;
    int ns = g_ns, lo = g_lo;
    int nrows = ns + (mat == 2 ? 1 : 0);
    const float* W    = (mat == 0) ? W0 : ((mat == 1) ? W1 : W2);
    const float* bias = (mat == 0) ? b0 : ((mat == 1) ? b1 : b2);
    float* dense = (mat == 0) ? g_q : ((mat == 1) ? g_k : g_v);
    int colbase = blockIdx.x * 128;
    int kbase = kb * 64;
    int mrows = min(nrows, RCAP);

    if      (mrows <= 64) proj_run<8>(x, W, bias, dense, lo, ns, mrows, mat, kbase, kb == 0, As_d, Bs, colbase);
    else if (mrows <= 80) proj_run<10>(x, W, bias, dense, lo, ns, mrows, mat, kbase, kb == 0, As_d, Bs, colbase);
    else if (mrows <= 96) proj_run<12>(x, W, bias, dense, lo, ns, mrows, mat, kbase, kb == 0, As_d, Bs, colbase);
    else                  proj_run<16>(x, W, bias, dense, lo, ns, mrows, mat, kbase, kb == 0, As_d, Bs, colbase);

    if (nrows > RCAP && kb == 0) {   // rare overflow: dense full-K STG for rows >= RCAP
        for (int idx = threadIdx.x; idx < (nrows - RCAP) * 128; idx += 256) {
            int r = RCAP + idx / 128, c = colbase + (idx & 127);
            float acc = bias[c] * ((r == ns && mat == 2) ? (float)S_LEN : 1.f);
            for (int k = 0; k < E_DIM; k++) {
                float xv;
                if (r < ns) xv = x[(size_t)(lo + r) * E_DIM + k];
                else { xv = 0.f; for (int p = 0; p < XS; p++) xv += g_xsump[p][k]; }
                acc += xv * W[(size_t)k * E_DIM + c];
            }
            dense[(size_t)r * E_DIM + c] = acc;
        }
    }
}

// ---------------- dot: q row (smem) . k row (smem), 64 dims, f32x2 ----------------
__device__ __forceinline__ float dot64(const float* qrow, const float* krow) {
    const ulonglong2* qp = (const ulonglong2*)qrow;
    const ulonglong2* kp = (const ulonglong2*)krow;
    unsigned long long s01 = 0ULL, s23 = 0ULL;
#pragma unroll
    for (int d4 = 0; d4 < 16; d4++) {
        ulonglong2 qv = qp[d4];
        ulonglong2 kv = kp[d4];
        ffma2(s01, qv.x, kv.x);
        ffma2(s23, qv.y, kv.y);
    }
    float e0, e1, e2, e3;
    upk2(s01, e0, e1); upk2(s23, e2, e3);
    return (e0 + e1) + (e2 + e3);
}

// ---------------- K3: per-head attention column sums (direct REDG out) ----------------
// grid (NHEADS, 8 row-blocks), 256 threads (8 warps, one row per warp per group)
__global__ void __launch_bounds__(256) k_attn() {
    extern __shared__ float sm[];
    float* kbuf = sm;                    // [128][KBSTR]
    float* qr   = kbuf + 128 * KBSTR;    // [8][KBSTR]

    int h = blockIdx.x, rb = blockIdx.y, ns = g_ns;
    int tid = threadIdx.x, w = tid >> 5, lane = tid & 31;
    int zc = S_LEN - ns;
    const float* qh = g_q + h * HD;
    const float* kh = g_k + h * HD;
    float* cg = g_c + h * S_LEN;

    if (ns <= 128) {
        // ---------- fast static path ----------
        for (int idx = tid; idx < ns * 16; idx += 256) {
            int j = idx >> 4, d4 = idx & 15;
            *(float4*)&kbuf[j * KBSTR + 4 * d4] =
                *(const float4*)&kh[(size_t)j * E_DIM + 4 * d4];
        }
        __syncthreads();
        int ngroups = (ns + 63) >> 6;
        for (int g = 0; g < ngroups; g++) {
            int i = g * 64 + rb * 8 + w;
            bool active = (i < ns);
            if (active && lane < 16)
                *(float4*)&qr[w * KBSTR + 4 * lane] =
                    *(const float4*)&qh[(size_t)i * E_DIM + 4 * lane];
            __syncwarp();
            if (active) {
                float sreg[4];
                float m = -1e30f;
                int nt = (ns + 31) >> 5;          // warp-uniform dot count
#pragma unroll
                for (int t = 0; t < 4; t++) {
                    if (t >= nt) break;
                    int j = t * 32 + lane;
                    int jj = (j < ns) ? j : (ns - 1);   // clamp: safe smem read
                    float s = dot64(&qr[w * KBSTR], &kbuf[jj * KBSTR]);
                    sreg[t] = (j < ns) ? s : -1e30f;
                    m = fmaxf(m, sreg[t]);
                }
#pragma unroll
                for (int o = 16; o > 0; o >>= 1)
                    m = fmaxf(m, __shfl_xor_sync(0xffffffffu, m, o));
                if (zc > 0) m = fmaxf(m, 0.f);    // masked entries are ZERO, not -inf
                float e[4];
                float Z = 0.f;
#pragma unroll
                for (int t = 0; t < 4; t++) {
                    if (t >= nt) break;
                    int j = t * 32 + lane;
                    e[t] = (j < ns) ? __expf(sreg[t] - m) : 0.f;
                    Z += e[t];
                }
#pragma unroll
                for (int o = 16; o > 0; o >>= 1)
                    Z += __shfl_xor_sync(0xffffffffu, Z, o);
                Z += (float)zc * __expf(-m);
                float invZ = 1.f / Z;
#pragma unroll
                for (int t = 0; t < 4; t++) {
                    if (t >= nt) break;
                    int j = t * 32 + lane;
                    if (j < ns) atomicAdd(&cg[j], e[t] * invZ);   // REDG
                }
                if (lane == 0) atomicAdd(&g_w0[h], __expf(-m) * invZ);
            }
        }
    } else {
        // ---------- general chunked path (ns > 128, effectively never) ----------
        const int JT = 128;
        __shared__ int s_loaded;
        if (tid == 0) s_loaded = -1;
        __syncthreads();
        int nchunks = (ns + JT - 1) / JT;
        int ngroups = (ns + 63) / 64;
        for (int g = 0; g < ngroups; g++) {
            int i = g * 64 + rb * 8 + w;
            bool active = (i < ns);
            if (active && lane < 16)
                *(float4*)&qr[w * KBSTR + 4 * lane] =
                    *(const float4*)&qh[(size_t)i * E_DIM + 4 * lane];
            __syncwarp();
            float m = -1e30f, Z = 0.f;
            for (int c = 0; c < nchunks; c++) {
                int c0 = c * JT, cl = min(JT, ns - c0);
                if (s_loaded != c) {
                    __syncthreads();
                    for (int idx = tid; idx < cl * 16; idx += 256) {
                        int j = idx >> 4, d4 = idx & 15;
                        *(float4*)&kbuf[j * KBSTR + 4 * d4] =
                            *(const float4*)&kh[(size_t)(c0 + j) * E_DIM + 4 * d4];
                    }
                    if (tid == 0) s_loaded = c;
                    __syncthreads();
                }
                if (active)
                    for (int j = lane; j < cl; j += 32) {
                        float s = dot64(&qr[w * KBSTR], &kbuf[j * KBSTR]);
                        float mn = fmaxf(m, s);
                        Z = Z * __expf(m - mn) + __expf(s - mn);
                        m = mn;
                    }
            }
            float mrow = 0.f, invZ = 0.f;
            if (active) {
                mrow = m;
#pragma unroll
                for (int o = 16; o > 0; o >>= 1)
                    mrow = fmaxf(mrow, __shfl_xor_sync(0xffffffffu, mrow, o));
                if (zc > 0) mrow = fmaxf(mrow, 0.f);
                float z = Z * __expf(m - mrow);
#pragma unroll
                for (int o = 16; o > 0; o >>= 1)
                    z += __shfl_xor_sync(0xffffffffu, z, o);
                z += (float)zc * __expf(-mrow);
                invZ = 1.f / z;
            }
            for (int c = 0; c < nchunks; c++) {
                int c0 = c * JT, cl = min(JT, ns - c0);
                if (s_loaded != c) {
                    __syncthreads();
                    for (int idx = tid; idx < cl * 16; idx += 256) {
                        int j = idx >> 4, d4 = idx & 15;
                        *(float4*)&kbuf[j * KBSTR + 4 * d4] =
                            *(const float4*)&kh[(size_t)(c0 + j) * E_DIM + 4 * d4];
                    }
                    if (tid == 0) s_loaded = c;
                    __syncthreads();
                }
                if (active)
                    for (int j = lane; j < cl; j += 32) {
                        float s = dot64(&qr[w * KBSTR], &kbuf[j * KBSTR]);
                        atomicAdd(&cg[c0 + j], __expf(s - mrow) * invZ);
                    }
            }
            if (active && lane == 0) atomicAdd(&g_w0[h], __expf(-mrow) * invZ);
        }
    }
}

// ---------------- K4: att slice from c/w0/V, then vecmat out = att @ Wo + bo ----------------
// grid (4 coltiles of 256, 32 kslices of 32), 256 threads
__global__ void __launch_bounds__(256) k_out(const float* __restrict__ Wo,
                                             const float* __restrict__ bo,
                                             float* __restrict__ dout) {
    __shared__ float c_s[S_LEN];
    __shared__ float red[8][32];
    __shared__ float att_s[32];
    int ky = blockIdx.y;
    int k0 = ky * 32;             // global att-dim base
    int h  = ky >> 1;             // owning head
    int ns = g_ns;
    int tid = threadIdx.x;
    int d = tid & 31, part = tid >> 5;   // 8 j-parts x 32 dims
    float w0 = g_w0[h];

    for (int i = tid; i < ns; i += 256) c_s[i] = g_c[h * S_LEN + i];
    __syncthreads();

    {
        float a0 = 0.f, a1 = 0.f;
        int j = part;
        for (; j + 8 < ns; j += 16) {
            a0 += (c_s[j]     - w0) * g_v[(size_t)j       * E_DIM + k0 + d];
            a1 += (c_s[j + 8] - w0) * g_v[(size_t)(j + 8) * E_DIM + k0 + d];
        }
        for (; j < ns; j += 8)
            a0 += (c_s[j] - w0) * g_v[(size_t)j * E_DIM + k0 + d];
        red[part][d] = a0 + a1;
    }
    __syncthreads();
    if (tid < 32) {
        float tot = red[0][d] + red[1][d] + red[2][d] + red[3][d]
                  + red[4][d] + red[5][d] + red[6][d] + red[7][d]
                  + w0 * g_v[(size_t)ns * E_DIM + k0 + d];   // vtot row
        att_s[d] = tot / (float)ns;
    }
    __syncthreads();

    int c = blockIdx.x * 256 + tid;
    float acc = (ky == 0) ? bo[c] : 0.f;
#pragma unroll
    for (int kk = 0; kk < 32; kk++)
        acc += att_s[kk] * Wo[(size_t)(k0 + kk) * E_DIM + c];
    atomicAdd(&dout[c], acc);
}

// ---------------- launch ----------------
#define PROJ_SMEM ((64 * ASTR + 64 * 128) * 4)
#define ATTN_SMEM ((128 * KBSTR + 8 * KBSTR) * 4)

extern "C" void kernel_launch(void* const* d_in, const int* in_sizes, int n_in,
                              void* d_out, int out_size) {
    const float* x   = (const float*)d_in[0];
    const int*   seg = (const int*)d_in[1];
    const int*   pos = (const int*)d_in[2];
    const float* Wq = (const float*)d_in[3];
    const float* bq = (const float*)d_in[4];
    const float* Wk = (const float*)d_in[5];
    const float* bk = (const float*)d_in[6];
    const float* Wv = (const float*)d_in[7];
    const float* bv = (const float*)d_in[8];
    const float* Wo = (const float*)d_in[9];
    const float* bo = (const float*)d_in[10];
    float* out = (float*)d_out;

    cudaFuncSetAttribute(k_proj, cudaFuncAttributeMaxDynamicSharedMemorySize, PROJ_SMEM);
    cudaFuncSetAttribute(k_attn, cudaFuncAttributeMaxDynamicSharedMemorySize, ATTN_SMEM);

    k_pre<<<128, 256>>>(x, seg, pos, out);
    k_proj<<<dim3(8, KSPLIT, 3), 256, PROJ_SMEM>>>(x, Wq, Wk, Wv, bq, bk, bv);
    k_attn<<<dim3(NHEADS, 8), 256, ATTN_SMEM>>>();
    k_out<<<dim3(4, 32), 256>>>(Wo, bo, out);
}